// round 2
// baseline (speedup 1.0000x reference)
#include <cuda_runtime.h>
#include <cstdint>
#include <cstddef>

// ---------------------------------------------------------------------------
// GAU denoising model, fp32 baseline.
// B=16, IMG=128, P=8 -> L=256 tokens, PD=192, H=768, E=1536, K=128, NL=24.
// Rows = B*L = 4096.
// ---------------------------------------------------------------------------

#define NB      16
#define LTOK    256
#define HD      768
#define ED      1536
#define KDIM    128
#define UVQK    3328      // 2E + 2K
#define ROWS    4096      // NB*LTOK
#define NLAYERS 24
#define PDIM    192

// Scratch (device globals; no allocation allowed)
__device__ float g_h   [(size_t)ROWS * HD];     // residual stream
__device__ float g_xn  [(size_t)ROWS * HD];     // rmsnorm output
__device__ float g_uvqk[(size_t)ROWS * UVQK];   // fused projection out
__device__ float g_attn[(size_t)ROWS * LTOK];   // softmax(qk^T)
__device__ float g_av  [(size_t)ROWS * ED];     // attn @ v (then * u)

// ---------------------------------------------------------------------------
// Patchify + patch_W GEMM + time-embedding bias.  One block per token row.
// ---------------------------------------------------------------------------
__global__ void patch_kernel(const float* __restrict__ x,
                             const int*   __restrict__ t_idx,
                             const float* __restrict__ pw,
                             const float* __restrict__ temb) {
    int r = blockIdx.x;                 // 0..4095
    int b = r >> 8, l = r & 255;
    int gy = l >> 4, gx = l & 15;
    int t = threadIdx.x;

    __shared__ float xr[PDIM];
    if (t < PDIM) {
        int py = t / 24, rem = t % 24, px = rem / 3, c = rem % 3;
        xr[t] = x[(((size_t)(b * 3 + c) * 128) + (gy * 8 + py)) * 128 + gx * 8 + px];
    }
    __syncthreads();

    const float* bias = temb + (size_t)t_idx[b] * HD;
    for (int col = t; col < HD; col += 256) {
        float s = 0.f;
        #pragma unroll 4
        for (int k = 0; k < PDIM; k++) s += xr[k] * pw[(size_t)k * HD + col];
        g_h[(size_t)r * HD + col] = s + bias[col];
    }
}

// ---------------------------------------------------------------------------
// RMSNorm: one block per row of 768.
// ---------------------------------------------------------------------------
__global__ void rmsnorm_kernel(const float* __restrict__ in,
                               const float* __restrict__ w,
                               float* __restrict__ outp) {
    int r = blockIdx.x, t = threadIdx.x;
    const float* row = in + (size_t)r * HD;
    float v0 = row[t], v1 = row[t + 256], v2 = row[t + 512];
    float ss = v0 * v0 + v1 * v1 + v2 * v2;

    __shared__ float red[256];
    red[t] = ss; __syncthreads();
    for (int o = 128; o > 0; o >>= 1) {
        if (t < o) red[t] += red[t + o];
        __syncthreads();
    }
    float rms = sqrtf(red[0] * (1.0f / HD));
    float inv = 1.f / (rms + 1e-6f);

    float* orow = outp + (size_t)r * HD;
    orow[t]       = v0 * inv * w[t];
    orow[t + 256] = v1 * inv * w[t + 256];
    orow[t + 512] = v2 * inv * w[t + 512];
}

// ---------------------------------------------------------------------------
// Activation: silu on u|v (cols 0..3071 in place), RoPE on q,k (cols 3072..3327).
// One block per row.
// ---------------------------------------------------------------------------
__global__ void act_kernel(float* __restrict__ uvqk) {
    int r = blockIdx.x, t = threadIdx.x;
    float* row = uvqk + (size_t)r * UVQK;

    #pragma unroll
    for (int i = 0; i < 12; i++) {
        int c = t + i * 256;
        float v = row[c];
        row[c] = v / (1.f + expf(-v));
    }

    if (t < 64) {
        int l = r & 255;
        float p1 = (float)(l >> 4), p2 = (float)(l & 15);
        int j = t;
        int jj = (j < 32) ? j : j - 32;
        // freqs[i] = exp(-ln(1000) * i / 31)
        float f  = expf(-6.907755278982137f * (float)jj * (1.0f / 31.0f));
        float a1 = p1 * f, a2 = p2 * f;
        // pe = [sin(p1 f),cos(p1 f) | sin(p2 f),cos(p2 f)]; apply_rope uses
        // sin = pe[:64] (emb1), cos = pe[64:] (emb2).
        float sv = (j < 32) ? sinf(a1) : cosf(a1);
        float cv = (j < 32) ? sinf(a2) : cosf(a2);

        float q1 = row[3072 + j], q2 = row[3136 + j];
        row[3072 + j] = q1 * cv - q2 * sv;
        row[3136 + j] = q2 * cv + q1 * sv;

        float k1 = row[3200 + j], k2 = row[3264 + j];
        row[3200 + j] = k1 * cv - k2 * sv;
        row[3264 + j] = k2 * cv + k1 * sv;
    }
}

// ---------------------------------------------------------------------------
// Attention scores + softmax. One block per query row; thread t owns key t.
// ---------------------------------------------------------------------------
__global__ void attn_kernel(const float* __restrict__ uvqk, float* __restrict__ attn) {
    int r = blockIdx.x;             // query row, 0..4095
    int b = r >> 8;
    int t = threadIdx.x;            // key index, 0..255

    __shared__ float qs[KDIM];
    __shared__ float red[256];
    const float* qrow = uvqk + (size_t)r * UVQK + 3072;
    if (t < KDIM) qs[t] = qrow[t];
    __syncthreads();

    const float* krow = uvqk + (size_t)(b * 256 + t) * UVQK + 3200;
    float s = 0.f;
    #pragma unroll 8
    for (int j = 0; j < KDIM; j++) s += qs[j] * krow[j];
    s *= 0.08838834764831845f;      // K^(-1/2)

    red[t] = s; __syncthreads();
    for (int o = 128; o > 0; o >>= 1) {
        if (t < o) red[t] = fmaxf(red[t], red[t + o]);
        __syncthreads();
    }
    float mx = red[0];
    __syncthreads();

    float e = expf(s - mx);
    red[t] = e; __syncthreads();
    for (int o = 128; o > 0; o >>= 1) {
        if (t < o) red[t] += red[t + o];
        __syncthreads();
    }
    float inv = 1.f / red[0];
    attn[(size_t)r * 256 + t] = e * inv;
}

// ---------------------------------------------------------------------------
// o = u * av (elementwise), one block per row.
// ---------------------------------------------------------------------------
__global__ void mul_kernel() {
    int r = blockIdx.x, t = threadIdx.x;
    float* av = g_av + (size_t)r * ED;
    const float* u = g_uvqk + (size_t)r * UVQK;
    #pragma unroll
    for (int i = 0; i < 6; i++) {
        int c = t + i * 256;
        av[c] *= u[c];
    }
}

// ---------------------------------------------------------------------------
// Generic fp32 SGEMM: C[M,N] = A[M,K] * B[K,N] (+= if ACC).
// 128x128 tile, BK=16, 256 threads, 8x8 per thread. Requires M%128==0,
// N%128==0, K%16==0, all lds multiples of 4. grid.z = batch with strides.
// ---------------------------------------------------------------------------
template <bool ACC>
__global__ void sgemm_kernel(const float* __restrict__ A,
                             const float* __restrict__ B,
                             float* __restrict__ C,
                             int M, int N, int K, int lda, int ldb, int ldc,
                             long sA, long sB, long sC) {
    A += (long)blockIdx.z * sA;
    B += (long)blockIdx.z * sB;
    C += (long)blockIdx.z * sC;

    __shared__ float As[16][128];
    __shared__ float Bs[16][128];

    int t = threadIdx.x;
    int bm0 = blockIdx.y * 128, bn0 = blockIdx.x * 128;
    int ty = t >> 4, tx = t & 15;

    float acc[8][8] = {};

    int arow = t >> 2, ak4 = (t & 3) * 4;   // A: 64 rows x 16 K per pass
    int brow = t >> 5, bn4 = (t & 31) * 4;  // B: 8 K-rows x 128 N per pass

    for (int kt = 0; kt < K; kt += 16) {
        #pragma unroll
        for (int p = 0; p < 2; p++) {
            float4 a = *(const float4*)&A[(size_t)(bm0 + arow + p * 64) * lda + kt + ak4];
            As[ak4 + 0][arow + p * 64] = a.x;
            As[ak4 + 1][arow + p * 64] = a.y;
            As[ak4 + 2][arow + p * 64] = a.z;
            As[ak4 + 3][arow + p * 64] = a.w;
        }
        #pragma unroll
        for (int p = 0; p < 2; p++) {
            float4 bv = *(const float4*)&B[(size_t)(kt + brow + p * 8) * ldb + bn0 + bn4];
            *(float4*)&Bs[brow + p * 8][bn4] = bv;
        }
        __syncthreads();

        #pragma unroll
        for (int kk = 0; kk < 16; kk++) {
            float a[8], b[8];
            *(float4*)&a[0] = *(const float4*)&As[kk][ty * 8];
            *(float4*)&a[4] = *(const float4*)&As[kk][ty * 8 + 4];
            *(float4*)&b[0] = *(const float4*)&Bs[kk][tx * 8];
            *(float4*)&b[4] = *(const float4*)&Bs[kk][tx * 8 + 4];
            #pragma unroll
            for (int i = 0; i < 8; i++)
                #pragma unroll
                for (int j = 0; j < 8; j++)
                    acc[i][j] += a[i] * b[j];
        }
        __syncthreads();
    }

    #pragma unroll
    for (int i = 0; i < 8; i++) {
        float* crow = &C[(size_t)(bm0 + ty * 8 + i) * ldc + bn0 + tx * 8];
        if (ACC) {
            #pragma unroll
            for (int j = 0; j < 8; j++) crow[j] += acc[i][j];
        } else {
            float4 c0 = {acc[i][0], acc[i][1], acc[i][2], acc[i][3]};
            float4 c1 = {acc[i][4], acc[i][5], acc[i][6], acc[i][7]};
            *(float4*)&crow[0] = c0;
            *(float4*)&crow[4] = c1;
        }
    }
}

// ---------------------------------------------------------------------------
// Final unpatch: rmsnorm'd h (g_xn) @ unpatch_W, scattered to (B,3,128,128).
// One block per token row; threads 0..191 each own one PD column.
// ---------------------------------------------------------------------------
__global__ void unpatch_kernel(const float* __restrict__ uw, float* __restrict__ out) {
    int r = blockIdx.x, t = threadIdx.x;
    int b = r >> 8, l = r & 255, gy = l >> 4, gx = l & 15;

    __shared__ float xr[HD];
    const float* row = g_xn + (size_t)r * HD;
    xr[t] = row[t]; xr[t + 256] = row[t + 256]; xr[t + 512] = row[t + 512];
    __syncthreads();

    if (t < PDIM) {
        float s = 0.f;
        #pragma unroll 4
        for (int k = 0; k < HD; k++) s += xr[k] * uw[(size_t)k * PDIM + t];
        int py = t / 24, rem = t % 24, px = rem / 3, c = rem % 3;
        out[(((size_t)(b * 3 + c) * 128) + (gy * 8 + py)) * 128 + gx * 8 + px] = s;
    }
}

// ---------------------------------------------------------------------------
// Host launcher (graph-capturable: kernel launches on default stream only).
// ---------------------------------------------------------------------------
extern "C" void kernel_launch(void* const* d_in, const int* in_sizes, int n_in,
                              void* d_out, int out_size) {
    const float* x        = (const float*)d_in[0];
    const int*   t_idx    = (const int*)  d_in[1];
    const float* patch_W  = (const float*)d_in[2];
    const float* t_emb    = (const float*)d_in[3];
    const float* Wuv      = (const float*)d_in[4];
    const float* Wout     = (const float*)d_in[5];
    const float* gnorm    = (const float*)d_in[6];
    const float* fnorm_w  = (const float*)d_in[7];
    const float* unpatchW = (const float*)d_in[8];
    float* out = (float*)d_out;

    float *h, *xn, *uvqk, *attn, *av;
    cudaGetSymbolAddress((void**)&h,    g_h);
    cudaGetSymbolAddress((void**)&xn,   g_xn);
    cudaGetSymbolAddress((void**)&uvqk, g_uvqk);
    cudaGetSymbolAddress((void**)&attn, g_attn);
    cudaGetSymbolAddress((void**)&av,   g_av);

    patch_kernel<<<ROWS, 256>>>(x, t_idx, patch_W, t_emb);

    for (int l = 0; l < NLAYERS; l++) {
        rmsnorm_kernel<<<ROWS, 256>>>(h, gnorm + (size_t)l * HD, xn);

        // uvqk = xn @ Wuv[l] : (4096 x 768) * (768 x 3328)
        sgemm_kernel<false><<<dim3(UVQK / 128, ROWS / 128, 1), 256>>>(
            xn, Wuv + (size_t)l * HD * UVQK, uvqk,
            ROWS, UVQK, HD, HD, UVQK, UVQK, 0, 0, 0);

        act_kernel<<<ROWS, 256>>>(uvqk);
        attn_kernel<<<ROWS, 256>>>(uvqk, attn);

        // av = attn @ v : per-batch (256 x 256) * (256 x 1536)
        sgemm_kernel<false><<<dim3(ED / 128, LTOK / 128, NB), 256>>>(
            attn, uvqk + ED, av,
            LTOK, ED, LTOK, LTOK, UVQK, ED,
            (long)LTOK * LTOK, (long)LTOK * UVQK, (long)LTOK * ED);

        mul_kernel<<<ROWS, 256>>>();

        // h += (u*av) @ Wout[l] : (4096 x 1536) * (1536 x 768)
        sgemm_kernel<true><<<dim3(HD / 128, ROWS / 128, 1), 256>>>(
            av, Wout + (size_t)l * ED * HD, h,
            ROWS, HD, ED, ED, HD, HD, 0, 0, 0);
    }

    rmsnorm_kernel<<<ROWS, 256>>>(h, fnorm_w, xn);
    unpatch_kernel<<<ROWS, 256>>>(unpatchW, out);
}

// round 4
// speedup vs baseline: 1.6095x; 1.6095x over previous
#include <cuda_runtime.h>
#include <cuda_bf16.h>
#include <cstdint>
#include <cstddef>

// ---------------------------------------------------------------------------
// GAU denoising model. Split-bf16 HMMA (mma.sync) GEMMs, fp32 elsewhere.
// Target is base sm_100 (tcgen05 unavailable in this build) -> Ampere-style
// mma.sync.m16n8k16.bf16 + ldmatrix + cp.async double buffering.
// B=16, L=256 tokens, PD=192, H=768, E=1536, K=128, NL=24, rows=4096.
// ---------------------------------------------------------------------------

#define NB      16
#define LTOK    256
#define HD      768
#define ED      1536
#define KDIM    128
#define UVQK    3328
#define ROWS    4096
#define NLAYERS 24
#define PDIM    192

// ----- scratch (device globals; allocation is forbidden) --------------------
__device__ float g_h   [(size_t)ROWS * HD];
__device__ float g_xn  [(size_t)ROWS * HD];
__device__ __nv_bfloat16 g_xnh[(size_t)ROWS * HD];
__device__ __nv_bfloat16 g_xnl[(size_t)ROWS * HD];
__device__ float g_uvqk[(size_t)ROWS * UVQK];
__device__ __nv_bfloat16 g_attnh[(size_t)ROWS * LTOK];
__device__ __nv_bfloat16 g_attnl[(size_t)ROWS * LTOK];
__device__ __nv_bfloat16 g_vth[(size_t)NB * ED * LTOK];   // v^T per batch [E][L]
__device__ __nv_bfloat16 g_vtl[(size_t)NB * ED * LTOK];
__device__ __nv_bfloat16 g_oh [(size_t)ROWS * ED];        // silu(u)*av
__device__ __nv_bfloat16 g_ol [(size_t)ROWS * ED];
__device__ __nv_bfloat16 g_wuvh[(size_t)NLAYERS * UVQK * HD];   // Wuv^T [N][K]
__device__ __nv_bfloat16 g_wuvl[(size_t)NLAYERS * UVQK * HD];
__device__ __nv_bfloat16 g_woh [(size_t)NLAYERS * HD * ED];     // Wout^T [N][K]
__device__ __nv_bfloat16 g_wol [(size_t)NLAYERS * HD * ED];

// ---------------------------------------------------------------------------
// PTX helpers (all sm_80-era: compile for base sm_100)
// ---------------------------------------------------------------------------
__device__ __forceinline__ uint32_t smem_u32(const void* p) {
    uint32_t a;
    asm("{ .reg .u64 t; cvta.to.shared.u64 t, %1; cvt.u32.u64 %0, t; }"
        : "=r"(a) : "l"(p));
    return a;
}
__device__ __forceinline__ void cp16(uint32_t dst, const void* src) {
    asm volatile("cp.async.cg.shared.global [%0], [%1], 16;"
                 :: "r"(dst), "l"(src) : "memory");
}
#define CP_COMMIT() asm volatile("cp.async.commit_group;" ::: "memory")
#define CP_WAIT(N)  asm volatile("cp.async.wait_group %0;" :: "n"(N) : "memory")

__device__ __forceinline__ void ldsm4(uint32_t* r, uint32_t addr) {
    asm volatile("ldmatrix.sync.aligned.m8n8.x4.shared.b16 {%0,%1,%2,%3}, [%4];"
                 : "=r"(r[0]), "=r"(r[1]), "=r"(r[2]), "=r"(r[3]) : "r"(addr));
}
__device__ __forceinline__ void mma16816(float* c, const uint32_t* a,
                                         uint32_t b0, uint32_t b1) {
    asm volatile(
        "mma.sync.aligned.m16n8k16.row.col.f32.bf16.bf16.f32 "
        "{%0,%1,%2,%3}, {%4,%5,%6,%7}, {%8,%9}, {%0,%1,%2,%3};"
        : "+f"(c[0]), "+f"(c[1]), "+f"(c[2]), "+f"(c[3])
        : "r"(a[0]), "r"(a[1]), "r"(a[2]), "r"(a[3]), "r"(b0), "r"(b1));
}

// ---------------------------------------------------------------------------
// Split-bf16 GEMM via mma.sync. C[M,N] from A[M,K] (row-major hi/lo) and
// B[N,K] (K-major hi/lo). D ~= Ah*Bh + Ah*Bl + Al*Bh.
// CTA tile 128x128, BK=32, 8 warps (2m x 4n), warp tile 64x32.
// EPI 0: C = D        EPI 1: O = silu(U)*D -> bf16 hi/lo      EPI 2: C += D
// Dyn smem: 2 stages x (Ah|Al|Bh|Bl), each tile 128 rows x 40-half stride.
// ---------------------------------------------------------------------------
#define SROW    40                      // padded row stride in halves (80B)
#define TILE_B  (128 * SROW * 2)        // 10240 B
#define O_AH    0
#define O_AL    (TILE_B)
#define O_BH    (2 * TILE_B)
#define O_BL    (3 * TILE_B)
#define STAGE_B (4 * TILE_B)            // 40960 B
#define GSMEM_SZ (2 * STAGE_B)          // 81920 B

template <int EPI>
__global__ void __launch_bounds__(256, 2) mma_gemm(
    const __nv_bfloat16* __restrict__ Ah, const __nv_bfloat16* __restrict__ Al,
    const __nv_bfloat16* __restrict__ Bh, const __nv_bfloat16* __restrict__ Bl,
    float* __restrict__ C, const float* __restrict__ U,
    __nv_bfloat16* __restrict__ Oh, __nv_bfloat16* __restrict__ Ol,
    int K, int lda, int ldb, int ldc, int ldu, int ldo,
    long sA, long sB, long sC, long sU, long sO) {

    extern __shared__ char smem[];
    uint32_t sb = smem_u32(smem);
    int t = threadIdx.x, lane = t & 31, wid = t >> 5;
    int wm = (wid >> 2) * 64, wn = (wid & 3) * 32;
    int bn0 = blockIdx.x * 128, bm0 = blockIdx.y * 128;
    long z = blockIdx.z;
    Ah += z * sA; Al += z * sA; Bh += z * sB; Bl += z * sB;
    if (EPI != 1) C += z * sC;
    if (EPI == 1) { U += z * sU; Oh += z * sO; Ol += z * sO; }

    float acc[4][4][4] = {};            // [mtile][ntile][c0..c3]

    // -------- stage loader: 4 tiles, 512 16B-chunks each, 2 per thread ------
    auto load_stage = [&](int buf, int kt) {
        uint32_t base = sb + buf * STAGE_B;
        #pragma unroll
        for (int i = 0; i < 2; i++) {
            int id = t + i * 256;
            int row = id >> 2, c = id & 3;
            uint32_t doff = (uint32_t)(row * SROW + c * 8) * 2;
            size_t aoff = (size_t)(bm0 + row) * lda + kt + c * 8;
            size_t boff = (size_t)(bn0 + row) * ldb + kt + c * 8;
            cp16(base + O_AH + doff, Ah + aoff);
            cp16(base + O_AL + doff, Al + aoff);
            cp16(base + O_BH + doff, Bh + boff);
            cp16(base + O_BL + doff, Bl + boff);
        }
        CP_COMMIT();
    };

    int nk = K / 32;
    load_stage(0, 0);

    for (int s = 0; s < nk; s++) {
        if (s + 1 < nk) { load_stage((s + 1) & 1, (s + 1) * 32); CP_WAIT(1); }
        else            { CP_WAIT(0); }
        __syncthreads();

        uint32_t base = sb + (s & 1) * STAGE_B;
        #pragma unroll
        for (int ks = 0; ks < 32; ks += 16) {
            // A fragments: row = wm + mt*16 + (lane&15), col = ks + (lane>>4)*8
            uint32_t ah[4][4], al[4][4];
            uint32_t arow = (uint32_t)(wm + (lane & 15));
            uint32_t acol = (uint32_t)(ks + ((lane >> 4) << 3));
            #pragma unroll
            for (int mt = 0; mt < 4; mt++) {
                uint32_t off = ((arow + mt * 16) * SROW + acol) * 2;
                ldsm4(ah[mt], base + O_AH + off);
                ldsm4(al[mt], base + O_AL + off);
            }
            #pragma unroll
            for (int ntp = 0; ntp < 2; ntp++) {
                // B fragments: row = wn + ntp*16 + ((lane>>4)&1)*8 + (lane&7)
                //              col = ks + ((lane>>3)&1)*8
                uint32_t brow = (uint32_t)(wn + ntp * 16 + ((lane >> 4) << 3) + (lane & 7));
                uint32_t bcol = (uint32_t)(ks + (((lane >> 3) & 1) << 3));
                uint32_t boff = (brow * SROW + bcol) * 2;
                uint32_t bh[4], bl[4];
                ldsm4(bh, base + O_BH + boff);
                ldsm4(bl, base + O_BL + boff);
                #pragma unroll
                for (int mt = 0; mt < 4; mt++) {
                    #pragma unroll
                    for (int ntl = 0; ntl < 2; ntl++) {
                        float* c = acc[mt][ntp * 2 + ntl];
                        mma16816(c, ah[mt], bh[ntl * 2], bh[ntl * 2 + 1]);
                        mma16816(c, ah[mt], bl[ntl * 2], bl[ntl * 2 + 1]);
                        mma16816(c, al[mt], bh[ntl * 2], bh[ntl * 2 + 1]);
                    }
                }
            }
        }
        __syncthreads();
    }

    // -------- epilogue: direct fragment stores (32B sector per segment) -----
    int g = lane >> 2, tc = lane & 3;
    #pragma unroll
    for (int mt = 0; mt < 4; mt++) {
        #pragma unroll
        for (int nt = 0; nt < 4; nt++) {
            float* c = acc[mt][nt];
            int r0 = bm0 + wm + mt * 16 + g;
            int c0 = bn0 + wn + nt * 8 + tc * 2;
            #pragma unroll
            for (int half = 0; half < 2; half++) {
                int r = r0 + half * 8;
                float v0 = c[half * 2], v1 = c[half * 2 + 1];
                if (EPI == 0) {
                    float2 st = {v0, v1};
                    *(float2*)&C[(size_t)r * ldc + c0] = st;
                } else if (EPI == 1) {
                    const float* up = &U[(size_t)r * ldu + c0];
                    float u0 = up[0], u1 = up[1];
                    float o0 = (u0 / (1.f + expf(-u0))) * v0;
                    float o1 = (u1 / (1.f + expf(-u1))) * v1;
                    __nv_bfloat16 h0 = __float2bfloat16(o0);
                    __nv_bfloat16 h1 = __float2bfloat16(o1);
                    __nv_bfloat162 hp; hp.x = h0; hp.y = h1;
                    __nv_bfloat162 lp;
                    lp.x = __float2bfloat16(o0 - __bfloat162float(h0));
                    lp.y = __float2bfloat16(o1 - __bfloat162float(h1));
                    *(__nv_bfloat162*)&Oh[(size_t)r * ldo + c0] = hp;
                    *(__nv_bfloat162*)&Ol[(size_t)r * ldo + c0] = lp;
                } else {
                    float2* p = (float2*)&C[(size_t)r * ldc + c0];
                    float2 old = *p;
                    old.x += v0; old.y += v1;
                    *p = old;
                }
            }
        }
    }
}

// ---------------------------------------------------------------------------
// Weight transpose + bf16 split: in [K,N] fp32 (per grid.z layer) -> out [N,K].
// ---------------------------------------------------------------------------
__global__ void wconv_kernel(const float* __restrict__ in,
                             __nv_bfloat16* __restrict__ oh,
                             __nv_bfloat16* __restrict__ ol, int K, int N) {
    __shared__ float tile[32][33];
    int n0 = blockIdx.x * 32, k0 = blockIdx.y * 32;
    size_t zoff = (size_t)blockIdx.z * K * N;
    const float* inz = in + zoff;
    __nv_bfloat16* ohz = oh + zoff;
    __nv_bfloat16* olz = ol + zoff;
    int tx = threadIdx.x, ty = threadIdx.y;
    #pragma unroll
    for (int i = 0; i < 4; i++)
        tile[ty + i * 8][tx] = inz[(size_t)(k0 + ty + i * 8) * N + n0 + tx];
    __syncthreads();
    #pragma unroll
    for (int i = 0; i < 4; i++) {
        float v = tile[tx][ty + i * 8];
        int n = n0 + ty + i * 8, k = k0 + tx;
        __nv_bfloat16 hi = __float2bfloat16(v);
        ohz[(size_t)n * K + k] = hi;
        olz[(size_t)n * K + k] = __float2bfloat16(v - __bfloat162float(hi));
    }
}

// ---------------------------------------------------------------------------
// v: silu + transpose + split.  vT[b][n][k] = silu(uvqk[(b*256+k)][1536+n])
// ---------------------------------------------------------------------------
__global__ void vt_kernel(const float* __restrict__ uvqk,
                          __nv_bfloat16* __restrict__ oh,
                          __nv_bfloat16* __restrict__ ol) {
    __shared__ float tile[32][33];
    int n0 = blockIdx.x * 32, k0 = blockIdx.y * 32, b = blockIdx.z;
    int tx = threadIdx.x, ty = threadIdx.y;
    #pragma unroll
    for (int i = 0; i < 4; i++) {
        int k = k0 + ty + i * 8;
        float v = uvqk[(size_t)(b * 256 + k) * UVQK + ED + n0 + tx];
        tile[ty + i * 8][tx] = v / (1.f + expf(-v));
    }
    __syncthreads();
    #pragma unroll
    for (int i = 0; i < 4; i++) {
        float v = tile[tx][ty + i * 8];
        int n = n0 + ty + i * 8, k = k0 + tx;
        size_t o = ((size_t)b * ED + n) * LTOK + k;
        __nv_bfloat16 hi = __float2bfloat16(v);
        oh[o] = hi;
        ol[o] = __float2bfloat16(v - __bfloat162float(hi));
    }
}

// ---------------------------------------------------------------------------
// Patchify + patch_W GEMM + time-embedding bias (validated round 1).
// ---------------------------------------------------------------------------
__global__ void patch_kernel(const float* __restrict__ x,
                             const int*   __restrict__ t_idx,
                             const float* __restrict__ pw,
                             const float* __restrict__ temb) {
    int r = blockIdx.x;
    int b = r >> 8, l = r & 255;
    int gy = l >> 4, gx = l & 15;
    int t = threadIdx.x;
    __shared__ float xr[PDIM];
    if (t < PDIM) {
        int py = t / 24, rem = t % 24, px = rem / 3, c = rem % 3;
        xr[t] = x[(((size_t)(b * 3 + c) * 128) + (gy * 8 + py)) * 128 + gx * 8 + px];
    }
    __syncthreads();
    const float* bias = temb + (size_t)t_idx[b] * HD;
    for (int col = t; col < HD; col += 256) {
        float s = 0.f;
        #pragma unroll 4
        for (int k = 0; k < PDIM; k++) s += xr[k] * pw[(size_t)k * HD + col];
        g_h[(size_t)r * HD + col] = s + bias[col];
    }
}

// ---------------------------------------------------------------------------
// RMSNorm: fp32 out + bf16 hi/lo out.
// ---------------------------------------------------------------------------
__global__ void rmsnorm_kernel(const float* __restrict__ in,
                               const float* __restrict__ w,
                               float* __restrict__ outp,
                               __nv_bfloat16* __restrict__ oh,
                               __nv_bfloat16* __restrict__ ol) {
    int r = blockIdx.x, t = threadIdx.x;
    const float* row = in + (size_t)r * HD;
    float v0 = row[t], v1 = row[t + 256], v2 = row[t + 512];
    __shared__ float red[256];
    red[t] = v0 * v0 + v1 * v1 + v2 * v2;
    __syncthreads();
    for (int o = 128; o > 0; o >>= 1) {
        if (t < o) red[t] += red[t + o];
        __syncthreads();
    }
    float inv = 1.f / (sqrtf(red[0] * (1.0f / HD)) + 1e-6f);
    size_t base = (size_t)r * HD;
    #pragma unroll
    for (int i = 0; i < 3; i++) {
        int c = t + i * 256;
        float v = (i == 0 ? v0 : i == 1 ? v1 : v2) * inv * w[c];
        outp[base + c] = v;
        __nv_bfloat16 hi = __float2bfloat16(v);
        oh[base + c] = hi;
        ol[base + c] = __float2bfloat16(v - __bfloat162float(hi));
    }
}

// ---------------------------------------------------------------------------
// RoPE in place on q,k cols of uvqk (validated round 1).
// ---------------------------------------------------------------------------
__global__ void rope_kernel(float* __restrict__ uvqk) {
    int r = blockIdx.x, j = threadIdx.x;        // 64 threads
    float* row = uvqk + (size_t)r * UVQK;
    int l = r & 255;
    float p1 = (float)(l >> 4), p2 = (float)(l & 15);
    int jj = (j < 32) ? j : j - 32;
    float f  = expf(-6.907755278982137f * (float)jj * (1.0f / 31.0f));
    float a1 = p1 * f, a2 = p2 * f;
    float sv = (j < 32) ? sinf(a1) : cosf(a1);
    float cv = (j < 32) ? sinf(a2) : cosf(a2);
    float q1 = row[3072 + j], q2 = row[3136 + j];
    row[3072 + j] = q1 * cv - q2 * sv;
    row[3136 + j] = q2 * cv + q1 * sv;
    float k1 = row[3200 + j], k2 = row[3264 + j];
    row[3200 + j] = k1 * cv - k2 * sv;
    row[3264 + j] = k2 * cv + k1 * sv;
}

// ---------------------------------------------------------------------------
// Attention scores + softmax, bf16 hi/lo output (validated math round 1).
// ---------------------------------------------------------------------------
__global__ void attn_kernel(const float* __restrict__ uvqk,
                            __nv_bfloat16* __restrict__ ah,
                            __nv_bfloat16* __restrict__ al) {
    int r = blockIdx.x;
    int b = r >> 8;
    int t = threadIdx.x;
    __shared__ float qs[KDIM];
    __shared__ float red[256];
    const float* qrow = uvqk + (size_t)r * UVQK + 3072;
    if (t < KDIM) qs[t] = qrow[t];
    __syncthreads();
    const float* krow = uvqk + (size_t)(b * 256 + t) * UVQK + 3200;
    float s = 0.f;
    #pragma unroll 8
    for (int j = 0; j < KDIM; j++) s += qs[j] * krow[j];
    s *= 0.08838834764831845f;
    red[t] = s; __syncthreads();
    for (int o = 128; o > 0; o >>= 1) {
        if (t < o) red[t] = fmaxf(red[t], red[t + o]);
        __syncthreads();
    }
    float mx = red[0];
    __syncthreads();
    float e = expf(s - mx);
    red[t] = e; __syncthreads();
    for (int o = 128; o > 0; o >>= 1) {
        if (t < o) red[t] += red[t + o];
        __syncthreads();
    }
    float p = e / red[0];
    __nv_bfloat16 hi = __float2bfloat16(p);
    ah[(size_t)r * 256 + t] = hi;
    al[(size_t)r * 256 + t] = __float2bfloat16(p - __bfloat162float(hi));
}

// ---------------------------------------------------------------------------
// Final unpatch (validated round 1).
// ---------------------------------------------------------------------------
__global__ void unpatch_kernel(const float* __restrict__ uw, float* __restrict__ out) {
    int r = blockIdx.x, t = threadIdx.x;
    int b = r >> 8, l = r & 255, gy = l >> 4, gx = l & 15;
    __shared__ float xr[HD];
    const float* row = g_xn + (size_t)r * HD;
    xr[t] = row[t]; xr[t + 256] = row[t + 256]; xr[t + 512] = row[t + 512];
    __syncthreads();
    if (t < PDIM) {
        float s = 0.f;
        #pragma unroll 4
        for (int k = 0; k < HD; k++) s += xr[k] * uw[(size_t)k * PDIM + t];
        int py = t / 24, rem = t % 24, px = rem / 3, c = rem % 3;
        out[(((size_t)(b * 3 + c) * 128) + (gy * 8 + py)) * 128 + gx * 8 + px] = s;
    }
}

// ---------------------------------------------------------------------------
// Host launcher
// ---------------------------------------------------------------------------
extern "C" void kernel_launch(void* const* d_in, const int* in_sizes, int n_in,
                              void* d_out, int out_size) {
    const float* x        = (const float*)d_in[0];
    const int*   t_idx    = (const int*)  d_in[1];
    const float* patch_W  = (const float*)d_in[2];
    const float* t_emb    = (const float*)d_in[3];
    const float* Wuv      = (const float*)d_in[4];
    const float* Wout     = (const float*)d_in[5];
    const float* gnorm    = (const float*)d_in[6];
    const float* fnorm_w  = (const float*)d_in[7];
    const float* unpatchW = (const float*)d_in[8];
    float* out = (float*)d_out;

    float *h, *xn, *uvqk;
    __nv_bfloat16 *xnh, *xnl, *ath, *atl, *vth, *vtl, *oh, *ol, *wuvh, *wuvl, *woh, *wol;
    cudaGetSymbolAddress((void**)&h,    g_h);
    cudaGetSymbolAddress((void**)&xn,   g_xn);
    cudaGetSymbolAddress((void**)&xnh,  g_xnh);
    cudaGetSymbolAddress((void**)&xnl,  g_xnl);
    cudaGetSymbolAddress((void**)&uvqk, g_uvqk);
    cudaGetSymbolAddress((void**)&ath,  g_attnh);
    cudaGetSymbolAddress((void**)&atl,  g_attnl);
    cudaGetSymbolAddress((void**)&vth,  g_vth);
    cudaGetSymbolAddress((void**)&vtl,  g_vtl);
    cudaGetSymbolAddress((void**)&oh,   g_oh);
    cudaGetSymbolAddress((void**)&ol,   g_ol);
    cudaGetSymbolAddress((void**)&wuvh, g_wuvh);
    cudaGetSymbolAddress((void**)&wuvl, g_wuvl);
    cudaGetSymbolAddress((void**)&woh,  g_woh);
    cudaGetSymbolAddress((void**)&wol,  g_wol);

    cudaFuncSetAttribute(mma_gemm<0>, cudaFuncAttributeMaxDynamicSharedMemorySize, GSMEM_SZ);
    cudaFuncSetAttribute(mma_gemm<1>, cudaFuncAttributeMaxDynamicSharedMemorySize, GSMEM_SZ);
    cudaFuncSetAttribute(mma_gemm<2>, cudaFuncAttributeMaxDynamicSharedMemorySize, GSMEM_SZ);

    // weight transpose + split (per replay; deterministic)
    wconv_kernel<<<dim3(UVQK / 32, HD / 32, NLAYERS), dim3(32, 8)>>>(Wuv, wuvh, wuvl, HD, UVQK);
    wconv_kernel<<<dim3(HD / 32, ED / 32, NLAYERS), dim3(32, 8)>>>(Wout, woh, wol, ED, HD);

    patch_kernel<<<ROWS, 256>>>(x, t_idx, patch_W, t_emb);

    for (int l = 0; l < NLAYERS; l++) {
        rmsnorm_kernel<<<ROWS, 256>>>(h, gnorm + (size_t)l * HD, xn, xnh, xnl);

        // uvqk = xn @ Wuv[l]   (4096 x 3328 x 768)
        mma_gemm<0><<<dim3(UVQK / 128, ROWS / 128, 1), 256, GSMEM_SZ>>>(
            xnh, xnl, wuvh + (size_t)l * UVQK * HD, wuvl + (size_t)l * UVQK * HD,
            uvqk, nullptr, nullptr, nullptr,
            HD, HD, HD, UVQK, 0, 0, 0, 0, 0, 0, 0);

        rope_kernel<<<ROWS, 64>>>(uvqk);
        attn_kernel<<<ROWS, 256>>>(uvqk, ath, atl);
        vt_kernel<<<dim3(ED / 32, LTOK / 32, NB), dim3(32, 8)>>>(uvqk, vth, vtl);

        // o = silu(u) * (attn @ v)   per batch (256 x 1536 x 256), fused epilogue
        mma_gemm<1><<<dim3(ED / 128, LTOK / 128, NB), 256, GSMEM_SZ>>>(
            ath, atl, vth, vtl,
            nullptr, uvqk, oh, ol,
            LTOK, LTOK, LTOK, 0, UVQK, ED,
            (long)LTOK * LTOK, (long)ED * LTOK, 0, (long)LTOK * UVQK, (long)LTOK * ED);

        // h += o @ Wout[l]   (4096 x 768 x 1536), fused residual
        mma_gemm<2><<<dim3(HD / 128, ROWS / 128, 1), 256, GSMEM_SZ>>>(
            oh, ol, woh + (size_t)l * HD * ED, wol + (size_t)l * HD * ED,
            h, nullptr, nullptr, nullptr,
            ED, ED, ED, HD, 0, 0, 0, 0, 0, 0, 0);
    }

    rmsnorm_kernel<<<ROWS, 256>>>(h, fnorm_w, xn, xnh, xnl);
    unpatch_kernel<<<ROWS, 256>>>(unpatchW, out);
}

// round 5
// speedup vs baseline: 1.6889x; 1.0493x over previous
#include <cuda_runtime.h>
#include <cuda_bf16.h>
#include <cstdint>
#include <cstddef>

// ---------------------------------------------------------------------------
// GAU denoising model. Split-bf16 HMMA (mma.sync) GEMMs, fp32 elsewhere.
// Round 5: spill-free inner loop, XOR-swizzled smem, 3-stage cp.async.
// B=16, L=256 tokens, PD=192, H=768, E=1536, K=128, NL=24, rows=4096.
// ---------------------------------------------------------------------------

#define NB      16
#define LTOK    256
#define HD      768
#define ED      1536
#define KDIM    128
#define UVQK    3328
#define ROWS    4096
#define NLAYERS 24
#define PDIM    192

// ----- scratch (device globals; allocation is forbidden) --------------------
__device__ float g_h   [(size_t)ROWS * HD];
__device__ float g_xn  [(size_t)ROWS * HD];
__device__ __nv_bfloat16 g_xnh[(size_t)ROWS * HD];
__device__ __nv_bfloat16 g_xnl[(size_t)ROWS * HD];
__device__ float g_uvqk[(size_t)ROWS * UVQK];
__device__ __nv_bfloat16 g_attnh[(size_t)ROWS * LTOK];
__device__ __nv_bfloat16 g_attnl[(size_t)ROWS * LTOK];
__device__ __nv_bfloat16 g_vth[(size_t)NB * ED * LTOK];   // v^T per batch [E][L]
__device__ __nv_bfloat16 g_vtl[(size_t)NB * ED * LTOK];
__device__ __nv_bfloat16 g_oh [(size_t)ROWS * ED];        // silu(u)*av
__device__ __nv_bfloat16 g_ol [(size_t)ROWS * ED];
__device__ __nv_bfloat16 g_wuvh[(size_t)NLAYERS * UVQK * HD];   // Wuv^T [N][K]
__device__ __nv_bfloat16 g_wuvl[(size_t)NLAYERS * UVQK * HD];
__device__ __nv_bfloat16 g_woh [(size_t)NLAYERS * HD * ED];     // Wout^T [N][K]
__device__ __nv_bfloat16 g_wol [(size_t)NLAYERS * HD * ED];

// ---------------------------------------------------------------------------
// PTX helpers (all sm_80-era: compile for base sm_100)
// ---------------------------------------------------------------------------
__device__ __forceinline__ uint32_t smem_u32(const void* p) {
    uint32_t a;
    asm("{ .reg .u64 t; cvta.to.shared.u64 t, %1; cvt.u32.u64 %0, t; }"
        : "=r"(a) : "l"(p));
    return a;
}
__device__ __forceinline__ void cp16(uint32_t dst, const void* src) {
    asm volatile("cp.async.cg.shared.global [%0], [%1], 16;"
                 :: "r"(dst), "l"(src) : "memory");
}
#define CP_COMMIT() asm volatile("cp.async.commit_group;" ::: "memory")
#define CP_WAIT(N)  asm volatile("cp.async.wait_group %0;" :: "n"(N) : "memory")

__device__ __forceinline__ void ldsm4(uint32_t* r, uint32_t addr) {
    asm volatile("ldmatrix.sync.aligned.m8n8.x4.shared.b16 {%0,%1,%2,%3}, [%4];"
                 : "=r"(r[0]), "=r"(r[1]), "=r"(r[2]), "=r"(r[3]) : "r"(addr));
}
__device__ __forceinline__ void mma16816(float* c, const uint32_t* a,
                                         uint32_t b0, uint32_t b1) {
    asm volatile(
        "mma.sync.aligned.m16n8k16.row.col.f32.bf16.bf16.f32 "
        "{%0,%1,%2,%3}, {%4,%5,%6,%7}, {%8,%9}, {%0,%1,%2,%3};"
        : "+f"(c[0]), "+f"(c[1]), "+f"(c[2]), "+f"(c[3])
        : "r"(a[0]), "r"(a[1]), "r"(a[2]), "r"(a[3]), "r"(b0), "r"(b1));
}

// ---------------------------------------------------------------------------
// Split-bf16 GEMM via mma.sync. C[M,N] from A[M,K] (row-major hi/lo) and
// B[N,K] (K-major hi/lo). D ~= Ah*Bh + Ah*Bl + Al*Bh.
// CTA tile 128x128, BK=32, 8 warps (2m x 4n), warp tile 64x32.
// Smem tile: 128 rows x 32 halves (64B/row), XOR-swizzled 16B chunks:
//   phys(r, c) = r*64 + ((c ^ ((r>>1)&3)) << 4)       (c = k-chunk 0..3)
// 3-stage cp.async pipeline, 2 loads in flight behind compute.
// EPI 0: C = D        EPI 1: O = silu(U)*D -> bf16 hi/lo      EPI 2: C += D
// ---------------------------------------------------------------------------
#define TILE_B   8192
#define O_AH     0
#define O_AL     (TILE_B)
#define O_BH     (2 * TILE_B)
#define O_BL     (3 * TILE_B)
#define STAGE_B  (4 * TILE_B)            // 32768 B
#define NSTAGE   3
#define GSMEM_SZ (NSTAGE * STAGE_B)      // 98304 B

__device__ __forceinline__ uint32_t swz(uint32_t r, uint32_t c) {
    return r * 64u + ((c ^ ((r >> 1) & 3u)) << 4);
}

template <int EPI>
__global__ void __launch_bounds__(256, 2) mma_gemm(
    const __nv_bfloat16* __restrict__ Ah, const __nv_bfloat16* __restrict__ Al,
    const __nv_bfloat16* __restrict__ Bh, const __nv_bfloat16* __restrict__ Bl,
    float* __restrict__ C, const float* __restrict__ U,
    __nv_bfloat16* __restrict__ Oh, __nv_bfloat16* __restrict__ Ol,
    int K, int lda, int ldb, int ldc, int ldu, int ldo,
    long sA, long sB, long sC, long sU, long sO) {

    extern __shared__ char smem[];
    uint32_t sb = smem_u32(smem);
    int t = threadIdx.x, lane = t & 31, wid = t >> 5;
    int wm = (wid >> 2) * 64, wn = (wid & 3) * 32;
    int bn0 = blockIdx.x * 128, bm0 = blockIdx.y * 128;
    long z = blockIdx.z;
    Ah += z * sA; Al += z * sA; Bh += z * sB; Bl += z * sB;
    if (EPI != 1) C += z * sC;
    if (EPI == 1) { U += z * sU; Oh += z * sO; Ol += z * sO; }

    float acc[4][4][4] = {};            // [mtile][ntile][c0..c3]

    // Precomputed per-thread loader offsets (row/chunk fixed across stages).
    uint32_t ld_row0 = (uint32_t)(t >> 2),        ld_c0 = (uint32_t)(t & 3);
    uint32_t ld_row1 = (uint32_t)((t + 256) >> 2), ld_c1 = (uint32_t)((t + 256) & 3);
    uint32_t ld_d0 = swz(ld_row0, ld_c0), ld_d1 = swz(ld_row1, ld_c1);

    auto load_stage = [&](int buf, int kt) {
        uint32_t base = sb + buf * STAGE_B;
        size_t a0 = (size_t)(bm0 + ld_row0) * lda + kt + ld_c0 * 8;
        size_t b0 = (size_t)(bn0 + ld_row0) * ldb + kt + ld_c0 * 8;
        size_t a1 = (size_t)(bm0 + ld_row1) * lda + kt + ld_c1 * 8;
        size_t b1 = (size_t)(bn0 + ld_row1) * ldb + kt + ld_c1 * 8;
        cp16(base + O_AH + ld_d0, Ah + a0);
        cp16(base + O_AL + ld_d0, Al + a0);
        cp16(base + O_BH + ld_d0, Bh + b0);
        cp16(base + O_BL + ld_d0, Bl + b0);
        cp16(base + O_AH + ld_d1, Ah + a1);
        cp16(base + O_AL + ld_d1, Al + a1);
        cp16(base + O_BH + ld_d1, Bh + b1);
        cp16(base + O_BL + ld_d1, Bl + b1);
        CP_COMMIT();
    };

    // Precomputed ldsm offsets for k-step 0; k-step 16 is offset ^ 32.
    uint32_t aoff[4], boff[2];
    {
        uint32_t ac = (uint32_t)(lane >> 4);                // A chunk (0..1)
        uint32_t ar = (uint32_t)(wm + (lane & 15));
        #pragma unroll
        for (int mt = 0; mt < 4; mt++) aoff[mt] = swz(ar + mt * 16, ac);
        uint32_t bc = (uint32_t)((lane >> 3) & 1);          // B chunk (0..1)
        uint32_t br = (uint32_t)(wn + ((lane >> 4) << 3) + (lane & 7));
        #pragma unroll
        for (int ntp = 0; ntp < 2; ntp++) boff[ntp] = swz(br + ntp * 16, bc);
    }

    int nk = K / 32;
    load_stage(0, 0);
    load_stage(1, 32);

    for (int s = 0; s < nk; s++) {
        CP_WAIT(1);                      // stage s resident; s+1 may be in flight
        __syncthreads();                 // also: everyone done reading stage s-1
        if (s + 2 < nk) load_stage((s + 2) % NSTAGE, (s + 2) * 32);
        else            CP_COMMIT();     // keep group accounting for the tail

        uint32_t base = sb + (s % NSTAGE) * STAGE_B;
        #pragma unroll
        for (int ks = 0; ks < 2; ks++) {
            uint32_t kx = ks ? 32u : 0u;
            uint32_t bh[8], bl[8];
            #pragma unroll
            for (int ntp = 0; ntp < 2; ntp++) {
                ldsm4(bh + ntp * 4, base + O_BH + (boff[ntp] ^ kx));
                ldsm4(bl + ntp * 4, base + O_BL + (boff[ntp] ^ kx));
            }
            #pragma unroll
            for (int mt = 0; mt < 4; mt++) {
                uint32_t ah[4], al[4];
                ldsm4(ah, base + O_AH + (aoff[mt] ^ kx));
                ldsm4(al, base + O_AL + (aoff[mt] ^ kx));
                #pragma unroll
                for (int nt = 0; nt < 4; nt++) {
                    float* c = acc[mt][nt];
                    mma16816(c, ah, bh[nt * 2], bh[nt * 2 + 1]);
                    mma16816(c, ah, bl[nt * 2], bl[nt * 2 + 1]);
                    mma16816(c, al, bh[nt * 2], bh[nt * 2 + 1]);
                }
            }
        }
    }

    // -------- epilogue: direct fragment stores (32B sector per segment) -----
    int g = lane >> 2, tc = lane & 3;
    #pragma unroll
    for (int mt = 0; mt < 4; mt++) {
        #pragma unroll
        for (int nt = 0; nt < 4; nt++) {
            float* c = acc[mt][nt];
            int r0 = bm0 + wm + mt * 16 + g;
            int c0 = bn0 + wn + nt * 8 + tc * 2;
            #pragma unroll
            for (int half = 0; half < 2; half++) {
                int r = r0 + half * 8;
                float v0 = c[half * 2], v1 = c[half * 2 + 1];
                if (EPI == 0) {
                    float2 st = {v0, v1};
                    *(float2*)&C[(size_t)r * ldc + c0] = st;
                } else if (EPI == 1) {
                    const float* up = &U[(size_t)r * ldu + c0];
                    float u0 = up[0], u1 = up[1];
                    float o0 = (u0 / (1.f + expf(-u0))) * v0;
                    float o1 = (u1 / (1.f + expf(-u1))) * v1;
                    __nv_bfloat16 h0 = __float2bfloat16(o0);
                    __nv_bfloat16 h1 = __float2bfloat16(o1);
                    __nv_bfloat162 hp; hp.x = h0; hp.y = h1;
                    __nv_bfloat162 lp;
                    lp.x = __float2bfloat16(o0 - __bfloat162float(h0));
                    lp.y = __float2bfloat16(o1 - __bfloat162float(h1));
                    *(__nv_bfloat162*)&Oh[(size_t)r * ldo + c0] = hp;
                    *(__nv_bfloat162*)&Ol[(size_t)r * ldo + c0] = lp;
                } else {
                    float2* p = (float2*)&C[(size_t)r * ldc + c0];
                    float2 old = *p;
                    old.x += v0; old.y += v1;
                    *p = old;
                }
            }
        }
    }
}

// ---------------------------------------------------------------------------
// Weight transpose + bf16 split: in [K,N] fp32 (per grid.z layer) -> out [N,K].
// ---------------------------------------------------------------------------
__global__ void wconv_kernel(const float* __restrict__ in,
                             __nv_bfloat16* __restrict__ oh,
                             __nv_bfloat16* __restrict__ ol, int K, int N) {
    __shared__ float tile[32][33];
    int n0 = blockIdx.x * 32, k0 = blockIdx.y * 32;
    size_t zoff = (size_t)blockIdx.z * K * N;
    const float* inz = in + zoff;
    __nv_bfloat16* ohz = oh + zoff;
    __nv_bfloat16* olz = ol + zoff;
    int tx = threadIdx.x, ty = threadIdx.y;
    #pragma unroll
    for (int i = 0; i < 4; i++)
        tile[ty + i * 8][tx] = inz[(size_t)(k0 + ty + i * 8) * N + n0 + tx];
    __syncthreads();
    #pragma unroll
    for (int i = 0; i < 4; i++) {
        float v = tile[tx][ty + i * 8];
        int n = n0 + ty + i * 8, k = k0 + tx;
        __nv_bfloat16 hi = __float2bfloat16(v);
        ohz[(size_t)n * K + k] = hi;
        olz[(size_t)n * K + k] = __float2bfloat16(v - __bfloat162float(hi));
    }
}

// ---------------------------------------------------------------------------
// v: silu + transpose + split.  vT[b][n][k] = silu(uvqk[(b*256+k)][1536+n])
// ---------------------------------------------------------------------------
__global__ void vt_kernel(const float* __restrict__ uvqk,
                          __nv_bfloat16* __restrict__ oh,
                          __nv_bfloat16* __restrict__ ol) {
    __shared__ float tile[32][33];
    int n0 = blockIdx.x * 32, k0 = blockIdx.y * 32, b = blockIdx.z;
    int tx = threadIdx.x, ty = threadIdx.y;
    #pragma unroll
    for (int i = 0; i < 4; i++) {
        int k = k0 + ty + i * 8;
        float v = uvqk[(size_t)(b * 256 + k) * UVQK + ED + n0 + tx];
        tile[ty + i * 8][tx] = v / (1.f + expf(-v));
    }
    __syncthreads();
    #pragma unroll
    for (int i = 0; i < 4; i++) {
        float v = tile[tx][ty + i * 8];
        int n = n0 + ty + i * 8, k = k0 + tx;
        size_t o = ((size_t)b * ED + n) * LTOK + k;
        __nv_bfloat16 hi = __float2bfloat16(v);
        oh[o] = hi;
        ol[o] = __float2bfloat16(v - __bfloat162float(hi));
    }
}

// ---------------------------------------------------------------------------
// Patchify + patch_W GEMM + time-embedding bias (validated round 1).
// ---------------------------------------------------------------------------
__global__ void patch_kernel(const float* __restrict__ x,
                             const int*   __restrict__ t_idx,
                             const float* __restrict__ pw,
                             const float* __restrict__ temb) {
    int r = blockIdx.x;
    int b = r >> 8, l = r & 255;
    int gy = l >> 4, gx = l & 15;
    int t = threadIdx.x;
    __shared__ float xr[PDIM];
    if (t < PDIM) {
        int py = t / 24, rem = t % 24, px = rem / 3, c = rem % 3;
        xr[t] = x[(((size_t)(b * 3 + c) * 128) + (gy * 8 + py)) * 128 + gx * 8 + px];
    }
    __syncthreads();
    const float* bias = temb + (size_t)t_idx[b] * HD;
    for (int col = t; col < HD; col += 256) {
        float s = 0.f;
        #pragma unroll 4
        for (int k = 0; k < PDIM; k++) s += xr[k] * pw[(size_t)k * HD + col];
        g_h[(size_t)r * HD + col] = s + bias[col];
    }
}

// ---------------------------------------------------------------------------
// RMSNorm: fp32 out + bf16 hi/lo out.
// ---------------------------------------------------------------------------
__global__ void rmsnorm_kernel(const float* __restrict__ in,
                               const float* __restrict__ w,
                               float* __restrict__ outp,
                               __nv_bfloat16* __restrict__ oh,
                               __nv_bfloat16* __restrict__ ol) {
    int r = blockIdx.x, t = threadIdx.x;
    const float* row = in + (size_t)r * HD;
    float v0 = row[t], v1 = row[t + 256], v2 = row[t + 512];
    __shared__ float red[256];
    red[t] = v0 * v0 + v1 * v1 + v2 * v2;
    __syncthreads();
    for (int o = 128; o > 0; o >>= 1) {
        if (t < o) red[t] += red[t + o];
        __syncthreads();
    }
    float inv = 1.f / (sqrtf(red[0] * (1.0f / HD)) + 1e-6f);
    size_t base = (size_t)r * HD;
    #pragma unroll
    for (int i = 0; i < 3; i++) {
        int c = t + i * 256;
        float v = (i == 0 ? v0 : i == 1 ? v1 : v2) * inv * w[c];
        outp[base + c] = v;
        __nv_bfloat16 hi = __float2bfloat16(v);
        oh[base + c] = hi;
        ol[base + c] = __float2bfloat16(v - __bfloat162float(hi));
    }
}

// ---------------------------------------------------------------------------
// RoPE in place on q,k cols of uvqk (validated round 1).
// ---------------------------------------------------------------------------
__global__ void rope_kernel(float* __restrict__ uvqk) {
    int r = blockIdx.x, j = threadIdx.x;        // 64 threads
    float* row = uvqk + (size_t)r * UVQK;
    int l = r & 255;
    float p1 = (float)(l >> 4), p2 = (float)(l & 15);
    int jj = (j < 32) ? j : j - 32;
    float f  = expf(-6.907755278982137f * (float)jj * (1.0f / 31.0f));
    float a1 = p1 * f, a2 = p2 * f;
    float sv = (j < 32) ? sinf(a1) : cosf(a1);
    float cv = (j < 32) ? sinf(a2) : cosf(a2);
    float q1 = row[3072 + j], q2 = row[3136 + j];
    row[3072 + j] = q1 * cv - q2 * sv;
    row[3136 + j] = q2 * cv + q1 * sv;
    float k1 = row[3200 + j], k2 = row[3264 + j];
    row[3200 + j] = k1 * cv - k2 * sv;
    row[3264 + j] = k2 * cv + k1 * sv;
}

// ---------------------------------------------------------------------------
// Attention scores + softmax, bf16 hi/lo output (validated math round 1).
// ---------------------------------------------------------------------------
__global__ void attn_kernel(const float* __restrict__ uvqk,
                            __nv_bfloat16* __restrict__ ah,
                            __nv_bfloat16* __restrict__ al) {
    int r = blockIdx.x;
    int b = r >> 8;
    int t = threadIdx.x;
    __shared__ float qs[KDIM];
    __shared__ float red[256];
    const float* qrow = uvqk + (size_t)r * UVQK + 3072;
    if (t < KDIM) qs[t] = qrow[t];
    __syncthreads();
    const float* krow = uvqk + (size_t)(b * 256 + t) * UVQK + 3200;
    float s = 0.f;
    #pragma unroll 8
    for (int j = 0; j < KDIM; j++) s += qs[j] * krow[j];
    s *= 0.08838834764831845f;
    red[t] = s; __syncthreads();
    for (int o = 128; o > 0; o >>= 1) {
        if (t < o) red[t] = fmaxf(red[t], red[t + o]);
        __syncthreads();
    }
    float mx = red[0];
    __syncthreads();
    float e = expf(s - mx);
    red[t] = e; __syncthreads();
    for (int o = 128; o > 0; o >>= 1) {
        if (t < o) red[t] += red[t + o];
        __syncthreads();
    }
    float p = e / red[0];
    __nv_bfloat16 hi = __float2bfloat16(p);
    ah[(size_t)r * 256 + t] = hi;
    al[(size_t)r * 256 + t] = __float2bfloat16(p - __bfloat162float(hi));
}

// ---------------------------------------------------------------------------
// Final unpatch (validated round 1).
// ---------------------------------------------------------------------------
__global__ void unpatch_kernel(const float* __restrict__ uw, float* __restrict__ out) {
    int r = blockIdx.x, t = threadIdx.x;
    int b = r >> 8, l = r & 255, gy = l >> 4, gx = l & 15;
    __shared__ float xr[HD];
    const float* row = g_xn + (size_t)r * HD;
    xr[t] = row[t]; xr[t + 256] = row[t + 256]; xr[t + 512] = row[t + 512];
    __syncthreads();
    if (t < PDIM) {
        float s = 0.f;
        #pragma unroll 4
        for (int k = 0; k < HD; k++) s += xr[k] * uw[(size_t)k * PDIM + t];
        int py = t / 24, rem = t % 24, px = rem / 3, c = rem % 3;
        out[(((size_t)(b * 3 + c) * 128) + (gy * 8 + py)) * 128 + gx * 8 + px] = s;
    }
}

// ---------------------------------------------------------------------------
// Host launcher
// ---------------------------------------------------------------------------
extern "C" void kernel_launch(void* const* d_in, const int* in_sizes, int n_in,
                              void* d_out, int out_size) {
    const float* x        = (const float*)d_in[0];
    const int*   t_idx    = (const int*)  d_in[1];
    const float* patch_W  = (const float*)d_in[2];
    const float* t_emb    = (const float*)d_in[3];
    const float* Wuv      = (const float*)d_in[4];
    const float* Wout     = (const float*)d_in[5];
    const float* gnorm    = (const float*)d_in[6];
    const float* fnorm_w  = (const float*)d_in[7];
    const float* unpatchW = (const float*)d_in[8];
    float* out = (float*)d_out;

    float *h, *xn, *uvqk;
    __nv_bfloat16 *xnh, *xnl, *ath, *atl, *vth, *vtl, *oh, *ol, *wuvh, *wuvl, *woh, *wol;
    cudaGetSymbolAddress((void**)&h,    g_h);
    cudaGetSymbolAddress((void**)&xn,   g_xn);
    cudaGetSymbolAddress((void**)&xnh,  g_xnh);
    cudaGetSymbolAddress((void**)&xnl,  g_xnl);
    cudaGetSymbolAddress((void**)&uvqk, g_uvqk);
    cudaGetSymbolAddress((void**)&ath,  g_attnh);
    cudaGetSymbolAddress((void**)&atl,  g_attnl);
    cudaGetSymbolAddress((void**)&vth,  g_vth);
    cudaGetSymbolAddress((void**)&vtl,  g_vtl);
    cudaGetSymbolAddress((void**)&oh,   g_oh);
    cudaGetSymbolAddress((void**)&ol,   g_ol);
    cudaGetSymbolAddress((void**)&wuvh, g_wuvh);
    cudaGetSymbolAddress((void**)&wuvl, g_wuvl);
    cudaGetSymbolAddress((void**)&woh,  g_woh);
    cudaGetSymbolAddress((void**)&wol,  g_wol);

    cudaFuncSetAttribute(mma_gemm<0>, cudaFuncAttributeMaxDynamicSharedMemorySize, GSMEM_SZ);
    cudaFuncSetAttribute(mma_gemm<1>, cudaFuncAttributeMaxDynamicSharedMemorySize, GSMEM_SZ);
    cudaFuncSetAttribute(mma_gemm<2>, cudaFuncAttributeMaxDynamicSharedMemorySize, GSMEM_SZ);

    // weight transpose + split (per replay; deterministic)
    wconv_kernel<<<dim3(UVQK / 32, HD / 32, NLAYERS), dim3(32, 8)>>>(Wuv, wuvh, wuvl, HD, UVQK);
    wconv_kernel<<<dim3(HD / 32, ED / 32, NLAYERS), dim3(32, 8)>>>(Wout, woh, wol, ED, HD);

    patch_kernel<<<ROWS, 256>>>(x, t_idx, patch_W, t_emb);

    for (int l = 0; l < NLAYERS; l++) {
        rmsnorm_kernel<<<ROWS, 256>>>(h, gnorm + (size_t)l * HD, xn, xnh, xnl);

        // uvqk = xn @ Wuv[l]   (4096 x 3328 x 768)
        mma_gemm<0><<<dim3(UVQK / 128, ROWS / 128, 1), 256, GSMEM_SZ>>>(
            xnh, xnl, wuvh + (size_t)l * UVQK * HD, wuvl + (size_t)l * UVQK * HD,
            uvqk, nullptr, nullptr, nullptr,
            HD, HD, HD, UVQK, 0, 0, 0, 0, 0, 0, 0);

        rope_kernel<<<ROWS, 64>>>(uvqk);
        attn_kernel<<<ROWS, 256>>>(uvqk, ath, atl);
        vt_kernel<<<dim3(ED / 32, LTOK / 32, NB), dim3(32, 8)>>>(uvqk, vth, vtl);

        // o = silu(u) * (attn @ v)   per batch (256 x 1536 x 256), fused epilogue
        mma_gemm<1><<<dim3(ED / 128, LTOK / 128, NB), 256, GSMEM_SZ>>>(
            ath, atl, vth, vtl,
            nullptr, uvqk, oh, ol,
            LTOK, LTOK, LTOK, 0, UVQK, ED,
            (long)LTOK * LTOK, (long)ED * LTOK, 0, (long)LTOK * UVQK, (long)LTOK * ED);

        // h += o @ Wout[l]   (4096 x 768 x 1536), fused residual
        mma_gemm<2><<<dim3(HD / 128, ROWS / 128, 1), 256, GSMEM_SZ>>>(
            oh, ol, woh + (size_t)l * HD * ED, wol + (size_t)l * HD * ED,
            h, nullptr, nullptr, nullptr,
            ED, ED, ED, HD, 0, 0, 0, 0, 0, 0, 0);
    }

    rmsnorm_kernel<<<ROWS, 256>>>(h, fnorm_w, xn, xnh, xnl);
    unpatch_kernel<<<ROWS, 256>>>(unpatchW, out);
}

// round 7
// speedup vs baseline: 2.1361x; 1.2648x over previous
#include <cuda_runtime.h>
#include <cuda_fp16.h>
#include <cstdint>
#include <cstddef>

// ---------------------------------------------------------------------------
// GAU denoising model. Single-term fp16 HMMA (mma.sync) GEMMs, fp32 elsewhere.
// Round 6 (re-run; prior attempt died to container infra): drop the hi/lo
// split (3x less MMA work); 4-stage cp.async pipeline.
// B=16, L=256 tokens, PD=192, H=768, E=1536, K=128, NL=24, rows=4096.
// ---------------------------------------------------------------------------

#define NB      16
#define LTOK    256
#define HD      768
#define ED      1536
#define KDIM    128
#define UVQK    3328
#define ROWS    4096
#define NLAYERS 24
#define PDIM    192

// ----- scratch (device globals; allocation is forbidden) --------------------
__device__ float g_h   [(size_t)ROWS * HD];
__device__ float g_xn  [(size_t)ROWS * HD];
__device__ __half g_xnh[(size_t)ROWS * HD];
__device__ float g_uvqk[(size_t)ROWS * UVQK];
__device__ __half g_attnh[(size_t)ROWS * LTOK];
__device__ __half g_vth[(size_t)NB * ED * LTOK];   // silu(v)^T per batch [E][L]
__device__ __half g_oh [(size_t)ROWS * ED];        // silu(u)*av
__device__ __half g_wuvh[(size_t)NLAYERS * UVQK * HD];   // Wuv^T [N][K]
__device__ __half g_woh [(size_t)NLAYERS * HD * ED];     // Wout^T [N][K]

// ---------------------------------------------------------------------------
// PTX helpers (sm_80-era; compile for base sm_100)
// ---------------------------------------------------------------------------
__device__ __forceinline__ uint32_t smem_u32(const void* p) {
    uint32_t a;
    asm("{ .reg .u64 t; cvta.to.shared.u64 t, %1; cvt.u32.u64 %0, t; }"
        : "=r"(a) : "l"(p));
    return a;
}
__device__ __forceinline__ void cp16(uint32_t dst, const void* src) {
    asm volatile("cp.async.cg.shared.global [%0], [%1], 16;"
                 :: "r"(dst), "l"(src) : "memory");
}
#define CP_COMMIT() asm volatile("cp.async.commit_group;" ::: "memory")
#define CP_WAIT(N)  asm volatile("cp.async.wait_group %0;" :: "n"(N) : "memory")

__device__ __forceinline__ void ldsm4(uint32_t* r, uint32_t addr) {
    asm volatile("ldmatrix.sync.aligned.m8n8.x4.shared.b16 {%0,%1,%2,%3}, [%4];"
                 : "=r"(r[0]), "=r"(r[1]), "=r"(r[2]), "=r"(r[3]) : "r"(addr));
}
__device__ __forceinline__ void mma16816(float* c, const uint32_t* a,
                                         uint32_t b0, uint32_t b1) {
    asm volatile(
        "mma.sync.aligned.m16n8k16.row.col.f32.f16.f16.f32 "
        "{%0,%1,%2,%3}, {%4,%5,%6,%7}, {%8,%9}, {%0,%1,%2,%3};"
        : "+f"(c[0]), "+f"(c[1]), "+f"(c[2]), "+f"(c[3])
        : "r"(a[0]), "r"(a[1]), "r"(a[2]), "r"(a[3]), "r"(b0), "r"(b1));
}

// ---------------------------------------------------------------------------
// fp16 GEMM via mma.sync. C[M,N] from A[M,K] (row-major) and B[N,K] (K-major).
// CTA tile 128x128, BK=32, 8 warps (2m x 4n), warp tile 64x32.
// Smem tile: 128 rows x 32 halves (64B/row), XOR-swizzled 16B chunks:
//   phys(r, c) = r*64 + ((c ^ ((r>>1)&3)) << 4)       (c = k-chunk 0..3)
// 4-stage cp.async pipeline, 3 loads in flight behind compute.
// EPI 0: C = D        EPI 1: O = silu(U)*D -> fp16      EPI 2: C += D
// ---------------------------------------------------------------------------
#define TILE_B   8192
#define O_A      0
#define O_B      (TILE_B)
#define STAGE_B  (2 * TILE_B)            // 16384 B
#define NSTAGE   4
#define GSMEM_SZ (NSTAGE * STAGE_B)      // 65536 B

__device__ __forceinline__ uint32_t swz(uint32_t r, uint32_t c) {
    return r * 64u + ((c ^ ((r >> 1) & 3u)) << 4);
}

template <int EPI>
__global__ void __launch_bounds__(256, 2) mma_gemm(
    const __half* __restrict__ A, const __half* __restrict__ B,
    float* __restrict__ C, const float* __restrict__ U,
    __half* __restrict__ Oh,
    int K, int lda, int ldb, int ldc, int ldu, int ldo,
    long sA, long sB, long sC, long sU, long sO) {

    extern __shared__ char smem[];
    uint32_t sb = smem_u32(smem);
    int t = threadIdx.x, lane = t & 31, wid = t >> 5;
    int wm = (wid >> 2) * 64, wn = (wid & 3) * 32;
    int bn0 = blockIdx.x * 128, bm0 = blockIdx.y * 128;
    long z = blockIdx.z;
    A += z * sA; B += z * sB;
    if (EPI != 1) C += z * sC;
    if (EPI == 1) { U += z * sU; Oh += z * sO; }

    float acc[4][4][4] = {};            // [mtile][ntile][c0..c3]

    // Per-thread loader offsets (fixed across stages).
    uint32_t ld_row0 = (uint32_t)(t >> 2),         ld_c0 = (uint32_t)(t & 3);
    uint32_t ld_row1 = (uint32_t)((t + 256) >> 2), ld_c1 = (uint32_t)((t + 256) & 3);
    uint32_t ld_d0 = swz(ld_row0, ld_c0), ld_d1 = swz(ld_row1, ld_c1);

    auto load_stage = [&](int buf, int kt) {
        uint32_t base = sb + buf * STAGE_B;
        cp16(base + O_A + ld_d0, A + (size_t)(bm0 + ld_row0) * lda + kt + ld_c0 * 8);
        cp16(base + O_B + ld_d0, B + (size_t)(bn0 + ld_row0) * ldb + kt + ld_c0 * 8);
        cp16(base + O_A + ld_d1, A + (size_t)(bm0 + ld_row1) * lda + kt + ld_c1 * 8);
        cp16(base + O_B + ld_d1, B + (size_t)(bn0 + ld_row1) * ldb + kt + ld_c1 * 8);
        CP_COMMIT();
    };

    // ldsm offsets for k-step 0; k-step 16 is offset ^ 32.
    uint32_t aoff[4], boff[2];
    {
        uint32_t ac = (uint32_t)(lane >> 4);                // A k-chunk (0..1)
        uint32_t ar = (uint32_t)(wm + (lane & 15));
        #pragma unroll
        for (int mt = 0; mt < 4; mt++) aoff[mt] = swz(ar + mt * 16, ac);
        uint32_t bc = (uint32_t)((lane >> 3) & 1);          // B k-chunk (0..1)
        uint32_t br = (uint32_t)(wn + ((lane >> 4) << 3) + (lane & 7));
        #pragma unroll
        for (int ntp = 0; ntp < 2; ntp++) boff[ntp] = swz(br + ntp * 16, bc);
    }

    int nk = K / 32;
    load_stage(0, 0);
    load_stage(1, 32);
    load_stage(2, 64);

    for (int s = 0; s < nk; s++) {
        CP_WAIT(2);                      // stage s resident; s+1, s+2 in flight
        __syncthreads();                 // everyone done reading stage s-1
        if (s + 3 < nk) load_stage((s + 3) % NSTAGE, (s + 3) * 32);
        else            CP_COMMIT();     // keep group accounting for the tail

        uint32_t base = sb + (s % NSTAGE) * STAGE_B;
        #pragma unroll
        for (int ks = 0; ks < 2; ks++) {
            uint32_t kx = ks ? 32u : 0u;
            uint32_t bf[8];
            #pragma unroll
            for (int ntp = 0; ntp < 2; ntp++)
                ldsm4(bf + ntp * 4, base + O_B + (boff[ntp] ^ kx));
            #pragma unroll
            for (int mt = 0; mt < 4; mt++) {
                uint32_t af[4];
                ldsm4(af, base + O_A + (aoff[mt] ^ kx));
                #pragma unroll
                for (int nt = 0; nt < 4; nt++)
                    mma16816(acc[mt][nt], af, bf[nt * 2], bf[nt * 2 + 1]);
            }
        }
    }

    // -------- epilogue: direct fragment stores (32B sector per segment) -----
    int g = lane >> 2, tc = lane & 3;
    #pragma unroll
    for (int mt = 0; mt < 4; mt++) {
        #pragma unroll
        for (int nt = 0; nt < 4; nt++) {
            float* c = acc[mt][nt];
            int r0 = bm0 + wm + mt * 16 + g;
            int c0 = bn0 + wn + nt * 8 + tc * 2;
            #pragma unroll
            for (int half = 0; half < 2; half++) {
                int r = r0 + half * 8;
                float v0 = c[half * 2], v1 = c[half * 2 + 1];
                if (EPI == 0) {
                    float2 st = {v0, v1};
                    *(float2*)&C[(size_t)r * ldc + c0] = st;
                } else if (EPI == 1) {
                    const float* up = &U[(size_t)r * ldu + c0];
                    float u0 = up[0], u1 = up[1];
                    float o0 = (u0 / (1.f + expf(-u0))) * v0;
                    float o1 = (u1 / (1.f + expf(-u1))) * v1;
                    __half2 hp;
                    hp.x = __float2half(o0);
                    hp.y = __float2half(o1);
                    *(__half2*)&Oh[(size_t)r * ldo + c0] = hp;
                } else {
                    float2* p = (float2*)&C[(size_t)r * ldc + c0];
                    float2 old = *p;
                    old.x += v0; old.y += v1;
                    *p = old;
                }
            }
        }
    }
}

// ---------------------------------------------------------------------------
// Weight transpose + fp16 convert: in [K,N] fp32 (per grid.z layer) -> [N,K].
// ---------------------------------------------------------------------------
__global__ void wconv_kernel(const float* __restrict__ in,
                             __half* __restrict__ oh, int K, int N) {
    __shared__ float tile[32][33];
    int n0 = blockIdx.x * 32, k0 = blockIdx.y * 32;
    size_t zoff = (size_t)blockIdx.z * K * N;
    const float* inz = in + zoff;
    __half* ohz = oh + zoff;
    int tx = threadIdx.x, ty = threadIdx.y;
    #pragma unroll
    for (int i = 0; i < 4; i++)
        tile[ty + i * 8][tx] = inz[(size_t)(k0 + ty + i * 8) * N + n0 + tx];
    __syncthreads();
    #pragma unroll
    for (int i = 0; i < 4; i++) {
        int n = n0 + ty + i * 8, k = k0 + tx;
        ohz[(size_t)n * K + k] = __float2half(tile[tx][ty + i * 8]);
    }
}

// ---------------------------------------------------------------------------
// v: silu + transpose + fp16.  vT[b][n][k] = silu(uvqk[(b*256+k)][1536+n])
// ---------------------------------------------------------------------------
__global__ void vt_kernel(const float* __restrict__ uvqk,
                          __half* __restrict__ oh) {
    __shared__ float tile[32][33];
    int n0 = blockIdx.x * 32, k0 = blockIdx.y * 32, b = blockIdx.z;
    int tx = threadIdx.x, ty = threadIdx.y;
    #pragma unroll
    for (int i = 0; i < 4; i++) {
        int k = k0 + ty + i * 8;
        float v = uvqk[(size_t)(b * 256 + k) * UVQK + ED + n0 + tx];
        tile[ty + i * 8][tx] = v / (1.f + expf(-v));
    }
    __syncthreads();
    #pragma unroll
    for (int i = 0; i < 4; i++) {
        int n = n0 + ty + i * 8, k = k0 + tx;
        oh[((size_t)b * ED + n) * LTOK + k] = __float2half(tile[tx][ty + i * 8]);
    }
}

// ---------------------------------------------------------------------------
// Patchify + patch_W GEMM + time-embedding bias (validated round 1).
// ---------------------------------------------------------------------------
__global__ void patch_kernel(const float* __restrict__ x,
                             const int*   __restrict__ t_idx,
                             const float* __restrict__ pw,
                             const float* __restrict__ temb) {
    int r = blockIdx.x;
    int b = r >> 8, l = r & 255;
    int gy = l >> 4, gx = l & 15;
    int t = threadIdx.x;
    __shared__ float xr[PDIM];
    if (t < PDIM) {
        int py = t / 24, rem = t % 24, px = rem / 3, c = rem % 3;
        xr[t] = x[(((size_t)(b * 3 + c) * 128) + (gy * 8 + py)) * 128 + gx * 8 + px];
    }
    __syncthreads();
    const float* bias = temb + (size_t)t_idx[b] * HD;
    for (int col = t; col < HD; col += 256) {
        float s = 0.f;
        #pragma unroll 4
        for (int k = 0; k < PDIM; k++) s += xr[k] * pw[(size_t)k * HD + col];
        g_h[(size_t)r * HD + col] = s + bias[col];
    }
}

// ---------------------------------------------------------------------------
// RMSNorm: fp32 out + fp16 out.
// ---------------------------------------------------------------------------
__global__ void rmsnorm_kernel(const float* __restrict__ in,
                               const float* __restrict__ w,
                               float* __restrict__ outp,
                               __half* __restrict__ oh) {
    int r = blockIdx.x, t = threadIdx.x;
    const float* row = in + (size_t)r * HD;
    float v0 = row[t], v1 = row[t + 256], v2 = row[t + 512];
    __shared__ float red[256];
    red[t] = v0 * v0 + v1 * v1 + v2 * v2;
    __syncthreads();
    for (int o = 128; o > 0; o >>= 1) {
        if (t < o) red[t] += red[t + o];
        __syncthreads();
    }
    float inv = 1.f / (sqrtf(red[0] * (1.0f / HD)) + 1e-6f);
    size_t base = (size_t)r * HD;
    #pragma unroll
    for (int i = 0; i < 3; i++) {
        int c = t + i * 256;
        float v = (i == 0 ? v0 : i == 1 ? v1 : v2) * inv * w[c];
        outp[base + c] = v;
        oh[base + c] = __float2half(v);
    }
}

// ---------------------------------------------------------------------------
// RoPE in place on q,k cols of uvqk (validated round 1).
// ---------------------------------------------------------------------------
__global__ void rope_kernel(float* __restrict__ uvqk) {
    int r = blockIdx.x, j = threadIdx.x;        // 64 threads
    float* row = uvqk + (size_t)r * UVQK;
    int l = r & 255;
    float p1 = (float)(l >> 4), p2 = (float)(l & 15);
    int jj = (j < 32) ? j : j - 32;
    float f  = expf(-6.907755278982137f * (float)jj * (1.0f / 31.0f));
    float a1 = p1 * f, a2 = p2 * f;
    float sv = (j < 32) ? sinf(a1) : cosf(a1);
    float cv = (j < 32) ? sinf(a2) : cosf(a2);
    float q1 = row[3072 + j], q2 = row[3136 + j];
    row[3072 + j] = q1 * cv - q2 * sv;
    row[3136 + j] = q2 * cv + q1 * sv;
    float k1 = row[3200 + j], k2 = row[3264 + j];
    row[3200 + j] = k1 * cv - k2 * sv;
    row[3264 + j] = k2 * cv + k1 * sv;
}

// ---------------------------------------------------------------------------
// Attention scores + softmax, fp16 output (validated math round 1).
// ---------------------------------------------------------------------------
__global__ void attn_kernel(const float* __restrict__ uvqk,
                            __half* __restrict__ ah) {
    int r = blockIdx.x;
    int b = r >> 8;
    int t = threadIdx.x;
    __shared__ float qs[KDIM];
    __shared__ float red[256];
    const float* qrow = uvqk + (size_t)r * UVQK + 3072;
    if (t < KDIM) qs[t] = qrow[t];
    __syncthreads();
    const float* krow = uvqk + (size_t)(b * 256 + t) * UVQK + 3200;
    float s = 0.f;
    #pragma unroll 8
    for (int j = 0; j < KDIM; j++) s += qs[j] * krow[j];
    s *= 0.08838834764831845f;
    red[t] = s; __syncthreads();
    for (int o = 128; o > 0; o >>= 1) {
        if (t < o) red[t] = fmaxf(red[t], red[t + o]);
        __syncthreads();
    }
    float mx = red[0];
    __syncthreads();
    float e = expf(s - mx);
    red[t] = e; __syncthreads();
    for (int o = 128; o > 0; o >>= 1) {
        if (t < o) red[t] += red[t + o];
        __syncthreads();
    }
    ah[(size_t)r * 256 + t] = __float2half(e / red[0]);
}

// ---------------------------------------------------------------------------
// Final unpatch (validated round 1).
// ---------------------------------------------------------------------------
__global__ void unpatch_kernel(const float* __restrict__ uw, float* __restrict__ out) {
    int r = blockIdx.x, t = threadIdx.x;
    int b = r >> 8, l = r & 255, gy = l >> 4, gx = l & 15;
    __shared__ float xr[HD];
    const float* row = g_xn + (size_t)r * HD;
    xr[t] = row[t]; xr[t + 256] = row[t + 256]; xr[t + 512] = row[t + 512];
    __syncthreads();
    if (t < PDIM) {
        float s = 0.f;
        #pragma unroll 4
        for (int k = 0; k < HD; k++) s += xr[k] * uw[(size_t)k * PDIM + t];
        int py = t / 24, rem = t % 24, px = rem / 3, c = rem % 3;
        out[(((size_t)(b * 3 + c) * 128) + (gy * 8 + py)) * 128 + gx * 8 + px] = s;
    }
}

// ---------------------------------------------------------------------------
// Host launcher
// ---------------------------------------------------------------------------
extern "C" void kernel_launch(void* const* d_in, const int* in_sizes, int n_in,
                              void* d_out, int out_size) {
    const float* x        = (const float*)d_in[0];
    const int*   t_idx    = (const int*)  d_in[1];
    const float* patch_W  = (const float*)d_in[2];
    const float* t_emb    = (const float*)d_in[3];
    const float* Wuv      = (const float*)d_in[4];
    const float* Wout     = (const float*)d_in[5];
    const float* gnorm    = (const float*)d_in[6];
    const float* fnorm_w  = (const float*)d_in[7];
    const float* unpatchW = (const float*)d_in[8];
    float* out = (float*)d_out;

    float *h, *xn, *uvqk;
    __half *xnh, *ath, *vth, *oh, *wuvh, *woh;
    cudaGetSymbolAddress((void**)&h,    g_h);
    cudaGetSymbolAddress((void**)&xn,   g_xn);
    cudaGetSymbolAddress((void**)&xnh,  g_xnh);
    cudaGetSymbolAddress((void**)&uvqk, g_uvqk);
    cudaGetSymbolAddress((void**)&ath,  g_attnh);
    cudaGetSymbolAddress((void**)&vth,  g_vth);
    cudaGetSymbolAddress((void**)&oh,   g_oh);
    cudaGetSymbolAddress((void**)&wuvh, g_wuvh);
    cudaGetSymbolAddress((void**)&woh,  g_woh);

    cudaFuncSetAttribute(mma_gemm<0>, cudaFuncAttributeMaxDynamicSharedMemorySize, GSMEM_SZ);
    cudaFuncSetAttribute(mma_gemm<1>, cudaFuncAttributeMaxDynamicSharedMemorySize, GSMEM_SZ);
    cudaFuncSetAttribute(mma_gemm<2>, cudaFuncAttributeMaxDynamicSharedMemorySize, GSMEM_SZ);

    // weight transpose + fp16 convert (per replay; deterministic)
    wconv_kernel<<<dim3(UVQK / 32, HD / 32, NLAYERS), dim3(32, 8)>>>(Wuv, wuvh, HD, UVQK);
    wconv_kernel<<<dim3(HD / 32, ED / 32, NLAYERS), dim3(32, 8)>>>(Wout, woh, ED, HD);

    patch_kernel<<<ROWS, 256>>>(x, t_idx, patch_W, t_emb);

    for (int l = 0; l < NLAYERS; l++) {
        rmsnorm_kernel<<<ROWS, 256>>>(h, gnorm + (size_t)l * HD, xn, xnh);

        // uvqk = xn @ Wuv[l]   (4096 x 3328 x 768)
        mma_gemm<0><<<dim3(UVQK / 128, ROWS / 128, 1), 256, GSMEM_SZ>>>(
            xnh, wuvh + (size_t)l * UVQK * HD,
            uvqk, nullptr, nullptr,
            HD, HD, HD, UVQK, 0, 0, 0, 0, 0, 0, 0);

        rope_kernel<<<ROWS, 64>>>(uvqk);
        attn_kernel<<<ROWS, 256>>>(uvqk, ath);
        vt_kernel<<<dim3(ED / 32, LTOK / 32, NB), dim3(32, 8)>>>(uvqk, vth);

        // o = silu(u) * (attn @ v)   per batch (256 x 1536 x 256), fused epilogue
        mma_gemm<1><<<dim3(ED / 128, LTOK / 128, NB), 256, GSMEM_SZ>>>(
            ath, vth,
            nullptr, uvqk, oh,
            LTOK, LTOK, LTOK, 0, UVQK, ED,
            (long)LTOK * LTOK, (long)ED * LTOK, 0, (long)LTOK * UVQK, (long)LTOK * ED);

        // h += o @ Wout[l]   (4096 x 768 x 1536), fused residual
        mma_gemm<2><<<dim3(HD / 128, ROWS / 128, 1), 256, GSMEM_SZ>>>(
            oh, woh + (size_t)l * HD * ED,
            h, nullptr, nullptr,
            ED, ED, ED, HD, 0, 0, 0, 0, 0, 0, 0);
    }

    rmsnorm_kernel<<<ROWS, 256>>>(h, fnorm_w, xn, xnh);
    unpatch_kernel<<<ROWS, 256>>>(unpatchW, out);
}